// round 16
// baseline (speedup 1.0000x reference)
#include <cuda_runtime.h>
#include <cuda_bf16.h>
#include <cstdint>

typedef __nv_bfloat16 bf16;

#define O_N 2000
#define T_N 6000
#define DIN 2048
#define DW 300
#define DWP 320
#define DG 512
#define H_DIM 512
#define L_EXTRA 4
#define E_N (2*T_N)
#define KP_EMB 2368

#define BN 128
#define BKC 64
#define ASTR 144

// ---------------- scratch (device globals) ----------------
__device__ __align__(16) bf16 g_eobj_h[O_N*DIN],  g_eobj_l[O_N*DIN];
__device__ __align__(16) bf16 g_epred_h[T_N*DIN], g_epred_l[T_N*DIN];
__device__ __align__(16) bf16 g_tobj_h[1000*DWP], g_tobj_l[1000*DWP];
__device__ __align__(16) bf16 g_trel_h[500*DWP],  g_trel_l[500*DWP];
__device__ __align__(16) bf16 g_objA_h[O_N*DIN],  g_objA_l[O_N*DIN];
__device__ __align__(16) bf16 g_pA_h[T_N*DIN],    g_pA_l[T_N*DIN];
__device__ __align__(16) bf16 g_h_h[T_N*512],     g_h_l[T_N*512];
__device__ __align__(16) bf16 g_p512_h[T_N*512],  g_p512_l[T_N*512];
__device__ __align__(16) bf16 g_pool_h[O_N*512],  g_pool_l[O_N*512];
__device__ __align__(16) bf16 g_o512_h[O_N*512],  g_o512_l[O_N*512];
__device__ __align__(16) float g_tblobj[1000*2048];
__device__ __align__(16) float g_tblrel[500*2048];
__device__ __align__(16) float g_objSO[O_N*1024];
#define WT_POOL 22544384
__device__ __align__(16) bf16 g_wt_h[WT_POOL], g_wt_l[WT_POOL];
__device__ __align__(16) float g_t[T_N * 1536];
__device__ int   g_cnt[O_N];
__device__ float g_inv[O_N];
__device__ int   g_off[O_N + 1];
__device__ int   g_objarr[E_N];
__device__ int   g_entries[E_N];

// ---------------- PTX helpers ----------------
__device__ __forceinline__ uint32_t smem_u32(const void* p) {
    uint32_t a;
    asm("{ .reg .u64 t; cvta.to.shared.u64 t, %1; cvt.u32.u64 %0, t; }" : "=r"(a) : "l"(p));
    return a;
}
__device__ __forceinline__ void cpa16(uint32_t dst, const void* src, uint32_t sz) {
    asm volatile("cp.async.cg.shared.global [%0], [%1], 16, %2;"
        :: "r"(dst), "l"(src), "r"(sz) : "memory");
}
__device__ __forceinline__ void cpa_commit() {
    asm volatile("cp.async.commit_group;" ::: "memory");
}
template<int N>
__device__ __forceinline__ void cpa_wait() {
    asm volatile("cp.async.wait_group %0;" :: "n"(N) : "memory");
}
__device__ __forceinline__ void ldsm4(uint32_t* r, uint32_t addr) {
    asm volatile("ldmatrix.sync.aligned.m8n8.x4.shared.b16 {%0,%1,%2,%3}, [%4];"
        : "=r"(r[0]), "=r"(r[1]), "=r"(r[2]), "=r"(r[3]) : "r"(addr));
}
__device__ __forceinline__ void mma16816(float* d, const uint32_t* a, const uint32_t* b) {
    asm volatile("mma.sync.aligned.m16n8k16.row.col.f32.bf16.bf16.f32 "
        "{%0,%1,%2,%3}, {%4,%5,%6,%7}, {%8,%9}, {%0,%1,%2,%3};"
        : "+f"(d[0]), "+f"(d[1]), "+f"(d[2]), "+f"(d[3])
        : "r"(a[0]), "r"(a[1]), "r"(a[2]), "r"(a[3]), "r"(b[0]), "r"(b[1]));
}
__device__ __forceinline__ void split1(float v, bf16& h, bf16& l) {
    h = __float2bfloat16_rn(v);
    l = __float2bfloat16_rn(v - __bfloat162float(h));
}

// ---------------- bf16x3 pipelined GEMM ----------------
// C = act(A @ Bt^T + bias + add0[idx0[row]] + add1[idx1[row]])
// MT=4: 128-row tile, 1 CTA/SM, 3-stage cp.async pipeline (deep load hiding)
// MT=2/1: 64/32-row tile, 2 CTA/SM, 2-stage (co-residency hides latency)
template<int MT>
__global__ __launch_bounds__(256, (MT == 4 ? 1 : 2))
void mma_gemm_kernel(int M, int K, int ldb, int do_relu, int skip_mid,
                     const bf16* __restrict__ A0h, const bf16* __restrict__ A0l, int lda,
                     const bf16* __restrict__ Bh, const bf16* __restrict__ Bl,
                     const float* __restrict__ bias,
                     const float* __restrict__ add0, const int* __restrict__ idx0, int idx0s, int add0ld, int add0off,
                     const float* __restrict__ add1, const int* __restrict__ idx1, int idx1s, int add1ld, int add1off,
                     float* __restrict__ Cf, bf16* __restrict__ Ch, bf16* __restrict__ Cl, int ldc,
                     float* __restrict__ auxf, bf16* __restrict__ auxh, bf16* __restrict__ auxl,
                     int aux_lo, int aux_hi)
{
    constexpr int BM = 32 * MT;
    constexpr int ATILE = BM * ASTR;
    constexpr int BTILE = 128 * ASTR;
    constexpr int STAGE = 2 * ATILE + 2 * BTILE;
    constexpr int NSTAGE = (MT == 4 ? 3 : 2);

    extern __shared__ char smem[];
    const uint32_t sb = smem_u32(smem);
    const int tid = threadIdx.x;
    const int lane = tid & 31;
    const int wid = tid >> 5;
    const int bm = blockIdx.y * BM;
    const int bn = blockIdx.x * BN;

    const int c = tid & 7;
    const int rl = tid >> 3;
    const bf16* pAh[MT]; const bf16* pAl[MT];
    uint32_t asz[MT];
    #pragma unroll
    for (int i = 0; i < MT; i++) {
        int arow = bm + rl + 32 * i;
        bool v = arow < M;
        asz[i] = v ? 16u : 0u;
        int ar = v ? arow : 0;
        pAh[i] = A0h + (size_t)ar * lda;
        pAl[i] = A0l + (size_t)ar * lda;
    }
    const bf16* pBh[4]; const bf16* pBl[4];
    #pragma unroll
    for (int i = 0; i < 4; i++) {
        int r = bn + rl + 32 * i;
        pBh[i] = Bh + (size_t)r * ldb;
        pBl[i] = Bl + (size_t)r * ldb;
    }

    float acc[MT][4][4];
    #pragma unroll
    for (int a = 0; a < MT; a++)
        #pragma unroll
        for (int b = 0; b < 4; b++)
            #pragma unroll
            for (int d = 0; d < 4; d++) acc[a][b][d] = 0.f;

    const int wr = wid & 1;
    const int wc = wid >> 1;
    const uint32_t a_l_off = (uint32_t)((lane & 15) * ASTR + (lane >> 4) * 16);
    const uint32_t b_l_off = (uint32_t)((((lane & 7) + ((lane >> 4) << 3)) * ASTR) + (((lane >> 3) & 1) << 4));

    const int NT = K / BKC;

    auto issue = [&](int it) {
        const uint32_t st = sb + (uint32_t)(it % NSTAGE) * STAGE;
        const int k0 = it * BKC + c * 8;
        #pragma unroll
        for (int i = 0; i < MT; i++) {
            uint32_t d = st + (uint32_t)((rl + 32 * i) * ASTR + c * 16);
            cpa16(d,         pAh[i] + k0, asz[i]);
            cpa16(d + ATILE, pAl[i] + k0, asz[i]);
        }
        #pragma unroll
        for (int i = 0; i < 4; i++) {
            uint32_t d = st + 2 * ATILE + (uint32_t)((rl + 32 * i) * ASTR + c * 16);
            cpa16(d,         pBh[i] + k0, 16u);
            cpa16(d + BTILE, pBl[i] + k0, 16u);
        }
        cpa_commit();
    };

    issue(0);
    if (NSTAGE == 3 && NT > 1) issue(1);

    for (int it = 0; it < NT; it++) {
        if (NSTAGE == 3) {
            if (it + 2 < NT)      { issue(it + 2); cpa_wait<2>(); }
            else if (it + 1 < NT) { cpa_wait<1>(); }
            else                  { cpa_wait<0>(); }
        } else {
            if (it + 1 < NT) { issue(it + 1); cpa_wait<1>(); }
            else             { cpa_wait<0>(); }
        }
        __syncthreads();

        const uint32_t st = sb + (uint32_t)(it % NSTAGE) * STAGE;
        const uint32_t aH = st + (uint32_t)(wr * 16 * MT * ASTR) + a_l_off;
        const uint32_t aL = aH + ATILE;
        const uint32_t bH = st + 2 * ATILE + (uint32_t)(wc * 32 * ASTR) + b_l_off;
        const uint32_t bL = bH + BTILE;

        #pragma unroll
        for (int ks = 0; ks < 4; ks++) {
            const uint32_t kb = ks * 32;
            uint32_t af[MT][4], bh2[2][4];
            #pragma unroll
            for (int mt = 0; mt < MT; mt++) ldsm4(af[mt], aH + (uint32_t)(mt * 16 * ASTR) + kb);
            #pragma unroll
            for (int np = 0; np < 2; np++) ldsm4(bh2[np], bH + (uint32_t)(np * 16 * ASTR) + kb);
            #pragma unroll
            for (int mt = 0; mt < MT; mt++)
                #pragma unroll
                for (int np = 0; np < 2; np++) {
                    mma16816(acc[mt][2 * np],     af[mt], &bh2[np][0]);
                    mma16816(acc[mt][2 * np + 1], af[mt], &bh2[np][2]);
                }
            uint32_t bl2[2][4];
            #pragma unroll
            for (int np = 0; np < 2; np++) ldsm4(bl2[np], bL + (uint32_t)(np * 16 * ASTR) + kb);
            #pragma unroll
            for (int mt = 0; mt < MT; mt++)
                #pragma unroll
                for (int np = 0; np < 2; np++) {
                    mma16816(acc[mt][2 * np],     af[mt], &bl2[np][0]);
                    mma16816(acc[mt][2 * np + 1], af[mt], &bl2[np][2]);
                }
            #pragma unroll
            for (int mt = 0; mt < MT; mt++) ldsm4(af[mt], aL + (uint32_t)(mt * 16 * ASTR) + kb);
            #pragma unroll
            for (int mt = 0; mt < MT; mt++)
                #pragma unroll
                for (int np = 0; np < 2; np++) {
                    mma16816(acc[mt][2 * np],     af[mt], &bh2[np][0]);
                    mma16816(acc[mt][2 * np + 1], af[mt], &bh2[np][2]);
                }
        }
        __syncthreads();
    }

    // ---- epilogue ----
    const int g = lane >> 2, qr = lane & 3;
    const int awidth = aux_hi - aux_lo;
    const float* a0p[MT][2];
    const float* a1p[MT][2];
    #pragma unroll
    for (int mt = 0; mt < MT; mt++)
        #pragma unroll
        for (int hh = 0; hh < 2; hh++) {
            int row = bm + wr * 16 * MT + mt * 16 + g + 8 * hh;
            int rr = (row < M) ? row : 0;
            a0p[mt][hh] = add0 ? add0 + (size_t)idx0[(size_t)rr * idx0s] * add0ld + add0off : nullptr;
            a1p[mt][hh] = add1 ? add1 + (size_t)idx1[(size_t)rr * idx1s] * add1ld + add1off : nullptr;
        }
    #pragma unroll
    for (int nt = 0; nt < 4; nt++) {
        const int col = bn + wc * 32 + nt * 8 + qr * 2;
        float2 bv = make_float2(0.f, 0.f);
        if (bias) bv = *reinterpret_cast<const float2*>(bias + col);
        const bool in_aux = (col >= aux_lo) && (col < aux_hi);
        #pragma unroll
        for (int mt = 0; mt < MT; mt++) {
            #pragma unroll
            for (int hh = 0; hh < 2; hh++) {
                const int row = bm + wr * 16 * MT + mt * 16 + g + 8 * hh;
                if (row >= M) continue;
                float v0 = acc[mt][nt][2 * hh]     + bv.x;
                float v1 = acc[mt][nt][2 * hh + 1] + bv.y;
                if (add0) {
                    float2 a = *reinterpret_cast<const float2*>(a0p[mt][hh] + col);
                    v0 += a.x; v1 += a.y;
                }
                if (add1) {
                    float2 a = *reinterpret_cast<const float2*>(a1p[mt][hh] + col);
                    v0 += a.x; v1 += a.y;
                }
                if (do_relu) { v0 = fmaxf(v0, 0.f); v1 = fmaxf(v1, 0.f); }
                if (Cf && !(skip_mid && in_aux))
                    *reinterpret_cast<float2*>(Cf + (size_t)row * ldc + col) = make_float2(v0, v1);
                if (Ch) {
                    bf16 h0, l0, h1, l1;
                    split1(v0, h0, l0); split1(v1, h1, l1);
                    __nv_bfloat162 ph; ph.x = h0; ph.y = h1;
                    __nv_bfloat162 pl; pl.x = l0; pl.y = l1;
                    *reinterpret_cast<__nv_bfloat162*>(Ch + (size_t)row * ldc + col) = ph;
                    *reinterpret_cast<__nv_bfloat162*>(Cl + (size_t)row * ldc + col) = pl;
                }
                if (in_aux) {
                    const int ac = col - aux_lo;
                    if (auxf)
                        *reinterpret_cast<float2*>(auxf + (size_t)row * awidth + ac) = make_float2(v0, v1);
                    if (auxh) {
                        bf16 h0, l0, h1, l1;
                        split1(v0, h0, l0); split1(v1, h1, l1);
                        __nv_bfloat162 ph; ph.x = h0; ph.y = h1;
                        __nv_bfloat162 pl; pl.x = l0; pl.y = l1;
                        *reinterpret_cast<__nv_bfloat162*>(auxh + (size_t)row * awidth + ac) = ph;
                        *reinterpret_cast<__nv_bfloat162*>(auxl + (size_t)row * awidth + ac) = pl;
                    }
                }
            }
        }
    }
}

// ---------------- mega prep kernels ----------------
struct TsJob { const float* src; bf16* dh; bf16* dl; int K, N, KP, tile0; };
struct TsArgs { TsJob j[32]; int nj; };
__global__ void mega_tsplit_kernel(TsArgs a) {
    const int b = blockIdx.x;
    int lo = 0;
    #pragma unroll 1
    for (int i = 1; i < a.nj; i++) if (a.j[i].tile0 <= b) lo = i;
    const TsJob jb = a.j[lo];
    const int t = b - jb.tile0;
    const int ntx = (jb.KP + 31) >> 5;
    const int tx = t % ntx, ty = t / ntx;
    __shared__ float tile[32][33];
    const int bk = tx * 32, bn = ty * 32;
    const int x = threadIdx.x & 31, y = threadIdx.x >> 5;
    for (int i = y; i < 32; i += 8) {
        int k = bk + i, n = bn + x;
        tile[i][x] = (k < jb.K && n < jb.N) ? jb.src[(size_t)k * jb.N + n] : 0.f;
    }
    __syncthreads();
    for (int i = y; i < 32; i += 8) {
        int n = bn + i, k = bk + x;
        if (n < jb.N && k < jb.KP) {
            float v = tile[x][i];
            bf16 hh, ll; split1(v, hh, ll);
            jb.dh[(size_t)n * jb.KP + k] = hh;
            jb.dl[(size_t)n * jb.KP + k] = ll;
        }
    }
}

struct SpJob { const float* src; bf16* dh; bf16* dl; int W, WP, n, blk0; };
struct SpArgs { SpJob j[4]; int nj; };
__global__ void mega_split_kernel(SpArgs a) {
    const int b = blockIdx.x;
    int lo = 0;
    #pragma unroll 1
    for (int i = 1; i < a.nj; i++) if (a.j[i].blk0 <= b) lo = i;
    const SpJob jb = a.j[lo];
    const int i = (b - jb.blk0) * 256 + threadIdx.x;
    if (i >= jb.n) return;
    const int v = i / jb.WP, c = i - v * jb.WP;
    float val = (c < jb.W) ? jb.src[(size_t)v * jb.W + c] : 0.f;
    bf16 hh, ll; split1(val, hh, ll);
    jb.dh[i] = hh; jb.dl[i] = ll;
}

// ---------------- deterministic scatter-mean pooling ----------------
__global__ void zero_int_kernel(int* p, int n) {
    int i = blockIdx.x * blockDim.x + threadIdx.x;
    if (i < n) p[i] = 0;
}
__global__ void build_count_kernel(const int* __restrict__ rels, int* __restrict__ objarr,
                                   int* __restrict__ cnt) {
    int e = blockIdx.x * blockDim.x + threadIdx.x;
    if (e >= E_N) return;
    int t = e >> 1;
    int v = rels[3 * t + ((e & 1) ? 2 : 0)];
    objarr[e] = v;
    atomicAdd(&cnt[v], 1);
}
__global__ void scan_kernel(const int* __restrict__ cnt, int* __restrict__ off,
                            float* __restrict__ inv) {
    __shared__ int buf[2][2048];
    int tid = threadIdx.x;
    for (int i = tid; i < 2048; i += 1024) {
        int c = (i < O_N) ? cnt[i] : 0;
        buf[0][i] = c;
        if (i < O_N) inv[i] = 1.0f / fmaxf((float)c, 1.0f);
    }
    __syncthreads();
    int src = 0;
    for (int d = 1; d < 2048; d <<= 1) {
        for (int i = tid; i < 2048; i += 1024) {
            int v = buf[src][i];
            if (i >= d) v += buf[src][i - d];
            buf[1 - src][i] = v;
        }
        src = 1 - src;
        __syncthreads();
    }
    for (int i = tid; i < O_N; i += 1024) off[i] = (i == 0) ? 0 : buf[src][i - 1];
    if (tid == 0) off[O_N] = buf[src][O_N - 1];
}
__global__ void rank_fill_kernel(const int* __restrict__ objarr, const int* __restrict__ off,
                                 int* __restrict__ entries) {
    int i = blockIdx.x * blockDim.x + threadIdx.x;
    if (i >= O_N) return;
    int w = off[i];
    for (int e = 0; e < E_N; e++)
        if (objarr[e] == i) entries[w++] = e;
}
// tbuf layout [T_N, 1536] = [new_s | new_p(skipped) | new_o]
__global__ void pool_gather_kernel(const float* __restrict__ t,
                                   const int* __restrict__ entries, const int* __restrict__ off,
                                   const float* __restrict__ inv,
                                   bf16* __restrict__ ph, bf16* __restrict__ pl) {
    int i = blockIdx.x;
    int c0 = threadIdx.x;
    int beg = off[i], end = off[i + 1];
    float s0 = 0.f, s1 = 0.f;
    for (int p = beg; p < end; p++) {
        int e = entries[p];
        int tr = e >> 1;
        const float* src = t + (size_t)tr * 1536 + ((e & 1) ? 1024 : 0);
        s0 += src[c0];
        s1 += src[c0 + 256];
    }
    float iv = inv[i];
    float v0 = s0 * iv, v1 = s1 * iv;
    bf16 h, l;
    split1(v0, h, l);
    ph[(size_t)i * 512 + c0] = h; pl[(size_t)i * 512 + c0] = l;
    split1(v1, h, l);
    ph[(size_t)i * 512 + c0 + 256] = h; pl[(size_t)i * 512 + c0 + 256] = l;
}

// ---------------- host glue ----------------
struct GPtr { bf16 *h, *l; };

#define SMEM_MT4 (3 * (2*128*ASTR + 2*128*ASTR))   // 3-stage: 221184 B
#define SMEM_MT2 (2 * (2*64*ASTR + 2*128*ASTR))
#define SMEM_MT1 (2 * (2*32*ASTR + 2*128*ASTR))

struct AddArg { const float* p; const int* idx; int s; int ld; int off; };

static inline void run_mma(int MT, int M, int Ntot, int K, int ldb, int relu,
                           GPtr A0, int lda, GPtr Bt,
                           const float* bias,
                           float* Cf, GPtr C, int ldc,
                           AddArg a0 = {nullptr, nullptr, 0, 0, 0},
                           AddArg a1 = {nullptr, nullptr, 0, 0, 0},
                           float* auxf = nullptr, GPtr aux = {nullptr, nullptr},
                           int aux_lo = 0, int aux_hi = 0, int skip_mid = 0)
{
    if (MT == 4) {
        dim3 grid(Ntot / BN, (M + 127) / 128);
        mma_gemm_kernel<4><<<grid, 256, SMEM_MT4>>>(M, K, ldb, relu, skip_mid,
            A0.h, A0.l, lda, Bt.h, Bt.l, bias,
            a0.p, a0.idx, a0.s, a0.ld, a0.off,
            a1.p, a1.idx, a1.s, a1.ld, a1.off,
            Cf, C.h, C.l, ldc, auxf, aux.h, aux.l, aux_lo, aux_hi);
    } else if (MT == 2) {
        dim3 grid(Ntot / BN, (M + 63) / 64);
        mma_gemm_kernel<2><<<grid, 256, SMEM_MT2>>>(M, K, ldb, relu, skip_mid,
            A0.h, A0.l, lda, Bt.h, Bt.l, bias,
            a0.p, a0.idx, a0.s, a0.ld, a0.off,
            a1.p, a1.idx, a1.s, a1.ld, a1.off,
            Cf, C.h, C.l, ldc, auxf, aux.h, aux.l, aux_lo, aux_hi);
    } else {
        dim3 grid(Ntot / BN, (M + 31) / 32);
        mma_gemm_kernel<1><<<grid, 256, SMEM_MT1>>>(M, K, ldb, relu, skip_mid,
            A0.h, A0.l, lda, Bt.h, Bt.l, bias,
            a0.p, a0.idx, a0.s, a0.ld, a0.off,
            a1.p, a1.idx, a1.s, a1.ld, a1.off,
            Cf, C.h, C.l, ldc, auxf, aux.h, aux.l, aux_lo, aux_hi);
    }
}

extern "C" void kernel_launch(void* const* d_in, const int* in_sizes, int n_in,
                              void* d_out, int out_size)
{
    const float* obj_embs  = (const float*)d_in[0];
    const float* pred_embs = (const float*)d_in[2];
    const int*   rels      = (const int*)d_in[4];
    const int*   objs      = (const int*)d_in[5];
    const float* obj_table = (const float*)d_in[6];
    const float* rel_table = (const float*)d_in[7];
    const float* Wf_obj    = (const float*)d_in[8];
    const float* bf_obj    = (const float*)d_in[9];
    const float* Wf_rel    = (const float*)d_in[10];
    const float* bf_rel    = (const float*)d_in[11];
    const float* W1a       = (const float*)d_in[12];
    const float* b1a       = (const float*)d_in[13];
    const float* W1b       = (const float*)d_in[14];
    const float* b1b       = (const float*)d_in[15];
    const float* W2a       = (const float*)d_in[16];
    const float* b2a       = (const float*)d_in[17];
    const float* W2b       = (const float*)d_in[18];
    const float* b2b       = (const float*)d_in[19];
    const float* Ws1a      = (const float*)d_in[20];
    const float* bs1a      = (const float*)d_in[21];
    const float* Ws1b      = (const float*)d_in[22];
    const float* bs1b      = (const float*)d_in[23];
    const float* Ws2a      = (const float*)d_in[24];
    const float* bs2a      = (const float*)d_in[25];
    const float* Ws2b      = (const float*)d_in[26];
    const float* bs2b      = (const float*)d_in[27];
    float* out = (float*)d_out;

    cudaFuncSetAttribute(mma_gemm_kernel<4>, cudaFuncAttributeMaxDynamicSharedMemorySize, SMEM_MT4);
    cudaFuncSetAttribute(mma_gemm_kernel<2>, cudaFuncAttributeMaxDynamicSharedMemorySize, SMEM_MT2);
    cudaFuncSetAttribute(mma_gemm_kernel<1>, cudaFuncAttributeMaxDynamicSharedMemorySize, SMEM_MT1);

    auto sym = [](const void* s) { void* p; cudaGetSymbolAddress(&p, s); return p; };
    GPtr eobj  = {(bf16*)sym(g_eobj_h),  (bf16*)sym(g_eobj_l)};
    GPtr epred = {(bf16*)sym(g_epred_h), (bf16*)sym(g_epred_l)};
    GPtr tobj  = {(bf16*)sym(g_tobj_h),  (bf16*)sym(g_tobj_l)};
    GPtr trel  = {(bf16*)sym(g_trel_h),  (bf16*)sym(g_trel_l)};
    GPtr objA  = {(bf16*)sym(g_objA_h),  (bf16*)sym(g_objA_l)};
    GPtr pA    = {(bf16*)sym(g_pA_h),    (bf16*)sym(g_pA_l)};
    GPtr hb    = {(bf16*)sym(g_h_h),     (bf16*)sym(g_h_l)};
    GPtr p512  = {(bf16*)sym(g_p512_h),  (bf16*)sym(g_p512_l)};
    GPtr pool  = {(bf16*)sym(g_pool_h),  (bf16*)sym(g_pool_l)};
    GPtr o512  = {(bf16*)sym(g_o512_h),  (bf16*)sym(g_o512_l)};
    float* tblobj = (float*)sym(g_tblobj);
    float* tblrel = (float*)sym(g_tblrel);
    float* objSO  = (float*)sym(g_objSO);
    bf16* wth = (bf16*)sym(g_wt_h);
    bf16* wtl = (bf16*)sym(g_wt_l);
    float* tbuf = (float*)sym(g_t);
    int* cnt = (int*)sym(g_cnt);
    int* off = (int*)sym(g_off);
    int* objarr = (int*)sym(g_objarr);
    int* entries = (int*)sym(g_entries);
    float* finv = (float*)sym(g_inv);

    // weight pool (bf16 elems)
    size_t po = 0;
    auto take = [&](size_t n) { GPtr r = {wth + po, wtl + po}; po += n; return r; };
    GPtr tWfobj  = take((size_t)DIN * KP_EMB);
    GPtr tWfrel  = take((size_t)DIN * KP_EMB);
    GPtr tW1a_p  = take((size_t)H_DIM * DIN);
    GPtr tW1a_so = take((size_t)1024 * DIN);
    GPtr tW1b    = take((size_t)1536 * H_DIM);
    GPtr tW2a    = take((size_t)H_DIM * H_DIM);
    GPtr tW2b    = take((size_t)DG * H_DIM);
    GPtr tWs1a_p  = take((size_t)L_EXTRA * H_DIM * DG);
    GPtr tWs1a_so = take((size_t)L_EXTRA * 1024 * DG);
    GPtr tWs1b    = take((size_t)L_EXTRA * 1536 * H_DIM);
    GPtr tWs2a    = take((size_t)L_EXTRA * H_DIM * H_DIM);
    GPtr tWs2b    = take((size_t)L_EXTRA * DG * H_DIM);

    // --- mega prep: all weight transpose+splits in ONE launch ---
    TsArgs ta; ta.nj = 0;
    int tile0 = 0;
    auto addts = [&](const float* src, GPtr dst, int K, int N, int KP) {
        TsJob& j = ta.j[ta.nj++];
        j.src = src; j.dh = dst.h; j.dl = dst.l; j.K = K; j.N = N; j.KP = KP; j.tile0 = tile0;
        tile0 += ((KP + 31) / 32) * ((N + 31) / 32);
    };
    addts(Wf_obj, tWfobj, DIN + DW, DIN, KP_EMB);
    addts(Wf_rel, tWfrel, DIN + DW, DIN, KP_EMB);
    addts(W1a + (size_t)DIN * H_DIM, tW1a_p, DIN, H_DIM, DIN);
    addts(W1a, tW1a_so, DIN, H_DIM, DIN);
    addts(W1a + (size_t)2 * DIN * H_DIM, {tW1a_so.h + (size_t)H_DIM * DIN, tW1a_so.l + (size_t)H_DIM * DIN}, DIN, H_DIM, DIN);
    addts(W1b, tW1b, H_DIM, 1536, H_DIM);
    addts(W2a, tW2a, H_DIM, H_DIM, H_DIM);
    addts(W2b, tW2b, H_DIM, DG, H_DIM);
    for (int i = 0; i < L_EXTRA; i++) {
        const float* Wi = Ws1a + (size_t)i * 3 * DG * H_DIM;
        GPtr p_i  = {tWs1a_p.h + (size_t)i * H_DIM * DG,  tWs1a_p.l + (size_t)i * H_DIM * DG};
        GPtr so_i = {tWs1a_so.h + (size_t)i * 1024 * DG,  tWs1a_so.l + (size_t)i * 1024 * DG};
        addts(Wi + (size_t)DG * H_DIM, p_i, DG, H_DIM, DG);
        addts(Wi, so_i, DG, H_DIM, DG);
        addts(Wi + (size_t)2 * DG * H_DIM, {so_i.h + (size_t)H_DIM * DG, so_i.l + (size_t)H_DIM * DG}, DG, H_DIM, DG);
        addts(Ws1b + (size_t)i * H_DIM * 1536, {tWs1b.h + (size_t)i * 1536 * H_DIM, tWs1b.l + (size_t)i * 1536 * H_DIM}, H_DIM, 1536, H_DIM);
        addts(Ws2a + (size_t)i * H_DIM * H_DIM, {tWs2a.h + (size_t)i * H_DIM * H_DIM, tWs2a.l + (size_t)i * H_DIM * H_DIM}, H_DIM, H_DIM, H_DIM);
        addts(Ws2b + (size_t)i * H_DIM * DG, {tWs2b.h + (size_t)i * DG * H_DIM, tWs2b.l + (size_t)i * DG * H_DIM}, H_DIM, DG, H_DIM);
    }
    mega_tsplit_kernel<<<tile0, 256>>>(ta);

    // --- mega activation splits in ONE launch ---
    SpArgs sa; sa.nj = 0;
    int blk0 = 0;
    auto addsp = [&](const float* src, GPtr dst, int V, int W, int WP) {
        SpJob& j = sa.j[sa.nj++];
        j.src = src; j.dh = dst.h; j.dl = dst.l; j.W = W; j.WP = WP; j.n = V * WP; j.blk0 = blk0;
        blk0 += (V * WP + 255) / 256;
    };
    addsp(obj_embs, eobj, O_N, DIN, DIN);
    addsp(pred_embs, epred, T_N, DIN, DIN);
    addsp(obj_table, tobj, 1000, DW, DWP);
    addsp(rel_table, trel, 500, DW, DWP);
    mega_split_kernel<<<blk0, 256>>>(sa);

    // --- CSR for deterministic pooling ---
    zero_int_kernel<<<(O_N + 255) / 256, 256>>>(cnt, O_N);
    build_count_kernel<<<(E_N + 255) / 256, 256>>>(rels, objarr, cnt);
    scan_kernel<<<1, 1024>>>(cnt, off, finv);
    rank_fill_kernel<<<(O_N + 255) / 256, 256>>>(objarr, off, entries);

    GPtr nullg = {nullptr, nullptr};
    AddArg noadd = {nullptr, nullptr, 0, 0, 0};

    // --- table contributions ---
    run_mma(2, 1000, DIN, DWP, KP_EMB, 0, tobj, DWP,
            {tWfobj.h + DIN, tWfobj.l + DIN}, nullptr, tblobj, nullg, DIN);
    run_mma(1, 500, DIN, DWP, KP_EMB, 0, trel, DWP,
            {tWfrel.h + DIN, tWfrel.l + DIN}, nullptr, tblrel, nullg, DIN);

    // --- embedding GEMMs (MT=4 + 3-stage pipeline) ---
    run_mma(4, O_N, DIN, DIN, KP_EMB, 1, eobj, DIN, tWfobj, bf_obj,
            nullptr, objA, DIN, {tblobj, objs, 1, DIN, 0});
    run_mma(4, T_N, DIN, DIN, KP_EMB, 1, epred, DIN, tWfrel, bf_rel,
            nullptr, pA, DIN, {tblrel, rels + 1, 3, DIN, 0});

    // --- layer 0 ---
    run_mma(2, O_N, 1024, DIN, DIN, 0, objA, DIN, tW1a_so, nullptr,
            objSO, nullg, 1024);
    run_mma(2, T_N, H_DIM, DIN, DIN, 1, pA, DIN, tW1a_p, b1a,
            nullptr, hb, H_DIM,
            {objSO, rels, 3, 1024, 0}, {objSO, rels + 2, 3, 1024, 512});
    run_mma(4, T_N, 1536, H_DIM, H_DIM, 1, hb, H_DIM, tW1b, b1b,
            tbuf, nullg, 1536, noadd, noadd, nullptr, p512, 512, 1024, 1);
    pool_gather_kernel<<<O_N, 256>>>(tbuf, entries, off, finv, pool.h, pool.l);
    run_mma(1, O_N, H_DIM, H_DIM, H_DIM, 1, pool, 512, tW2a, b2a,
            nullptr, hb, H_DIM);
    run_mma(1, O_N, DG, H_DIM, H_DIM, 1, hb, 512, tW2b, b2b,
            nullptr, o512, DG);

    // --- extra layers ---
    for (int i = 0; i < L_EXTRA; i++) {
        const bool last = (i == L_EXTRA - 1);
        GPtr p_i  = {tWs1a_p.h + (size_t)i * H_DIM * DG,  tWs1a_p.l + (size_t)i * H_DIM * DG};
        GPtr so_i = {tWs1a_so.h + (size_t)i * 1024 * DG,  tWs1a_so.l + (size_t)i * 1024 * DG};
        GPtr w1b = {tWs1b.h + (size_t)i * 1536 * H_DIM,   tWs1b.l + (size_t)i * 1536 * H_DIM};
        GPtr w2a = {tWs2a.h + (size_t)i * H_DIM * H_DIM,  tWs2a.l + (size_t)i * H_DIM * H_DIM};
        GPtr w2b = {tWs2b.h + (size_t)i * DG * H_DIM,     tWs2b.l + (size_t)i * DG * H_DIM};

        run_mma(2, O_N, 1024, DG, DG, 0, o512, DG, so_i, nullptr,
                objSO, nullg, 1024);
        run_mma(2, T_N, H_DIM, DG, DG, 1, p512, DG, p_i, bs1a + (size_t)i * H_DIM,
                nullptr, hb, H_DIM,
                {objSO, rels, 3, 1024, 0}, {objSO, rels + 2, 3, 1024, 512});
        run_mma(4, T_N, 1536, H_DIM, H_DIM, 1, hb, H_DIM, w1b, bs1b + (size_t)i * 1536,
                tbuf, nullg, 1536, noadd, noadd,
                last ? (out + (size_t)O_N * DG) : nullptr,
                last ? nullg : p512, 512, 1024, 1);
        pool_gather_kernel<<<O_N, 256>>>(tbuf, entries, off, finv, pool.h, pool.l);
        run_mma(1, O_N, H_DIM, H_DIM, H_DIM, 1, pool, 512, w2a, bs2a + (size_t)i * H_DIM,
                nullptr, hb, H_DIM);
        run_mma(1, O_N, DG, H_DIM, H_DIM, 1, hb, 512, w2b, bs2b + (size_t)i * DG,
                last ? out : nullptr, last ? nullg : o512, DG);
    }
}

// round 17
// speedup vs baseline: 1.0042x; 1.0042x over previous
#include <cuda_runtime.h>
#include <cuda_bf16.h>
#include <cstdint>

typedef __nv_bfloat16 bf16;

#define O_N 2000
#define T_N 6000
#define DIN 2048
#define DW 300
#define DWP 320
#define DG 512
#define H_DIM 512
#define L_EXTRA 4
#define E_N (2*T_N)
#define KP_EMB 2368

#define BN 128
#define BKC 64
#define ASTR 144

// ---------------- scratch (device globals) ----------------
__device__ __align__(16) bf16 g_eobj_h[O_N*DIN],  g_eobj_l[O_N*DIN];
__device__ __align__(16) bf16 g_epred_h[T_N*DIN], g_epred_l[T_N*DIN];
__device__ __align__(16) bf16 g_tobj_h[1000*DWP], g_tobj_l[1000*DWP];
__device__ __align__(16) bf16 g_trel_h[500*DWP],  g_trel_l[500*DWP];
__device__ __align__(16) bf16 g_objA_h[O_N*DIN],  g_objA_l[O_N*DIN];
__device__ __align__(16) bf16 g_pA_h[T_N*DIN],    g_pA_l[T_N*DIN];
__device__ __align__(16) bf16 g_h_h[T_N*512],     g_h_l[T_N*512];
__device__ __align__(16) bf16 g_p512_h[T_N*512],  g_p512_l[T_N*512];
__device__ __align__(16) bf16 g_pool_h[O_N*512],  g_pool_l[O_N*512];
__device__ __align__(16) bf16 g_o512_h[O_N*512],  g_o512_l[O_N*512];
__device__ __align__(16) float g_tblobj[1000*2048];
__device__ __align__(16) float g_tblrel[500*2048];
__device__ __align__(16) float g_objSO[O_N*1024];
#define WT_POOL 22544384
__device__ __align__(16) bf16 g_wt_h[WT_POOL], g_wt_l[WT_POOL];
__device__ __align__(16) float g_t[T_N * 1536];
__device__ int   g_cnt[O_N];
__device__ float g_inv[O_N];
__device__ int   g_off[O_N + 1];
__device__ int   g_objarr[E_N];
__device__ int   g_entries[E_N];

// ---------------- PTX helpers ----------------
__device__ __forceinline__ uint32_t smem_u32(const void* p) {
    uint32_t a;
    asm("{ .reg .u64 t; cvta.to.shared.u64 t, %1; cvt.u32.u64 %0, t; }" : "=r"(a) : "l"(p));
    return a;
}
__device__ __forceinline__ void cpa16(uint32_t dst, const void* src, uint32_t sz) {
    asm volatile("cp.async.cg.shared.global [%0], [%1], 16, %2;"
        :: "r"(dst), "l"(src), "r"(sz) : "memory");
}
__device__ __forceinline__ void cpa_commit() {
    asm volatile("cp.async.commit_group;" ::: "memory");
}
template<int N>
__device__ __forceinline__ void cpa_wait() {
    asm volatile("cp.async.wait_group %0;" :: "n"(N) : "memory");
}
__device__ __forceinline__ void ldsm4(uint32_t* r, uint32_t addr) {
    asm volatile("ldmatrix.sync.aligned.m8n8.x4.shared.b16 {%0,%1,%2,%3}, [%4];"
        : "=r"(r[0]), "=r"(r[1]), "=r"(r[2]), "=r"(r[3]) : "r"(addr));
}
__device__ __forceinline__ void mma16816(float* d, const uint32_t* a, const uint32_t* b) {
    asm volatile("mma.sync.aligned.m16n8k16.row.col.f32.bf16.bf16.f32 "
        "{%0,%1,%2,%3}, {%4,%5,%6,%7}, {%8,%9}, {%0,%1,%2,%3};"
        : "+f"(d[0]), "+f"(d[1]), "+f"(d[2]), "+f"(d[3])
        : "r"(a[0]), "r"(a[1]), "r"(a[2]), "r"(a[3]), "r"(b[0]), "r"(b[1]));
}
__device__ __forceinline__ void split1(float v, bf16& h, bf16& l) {
    h = __float2bfloat16_rn(v);
    l = __float2bfloat16_rn(v - __bfloat162float(h));
}

// ---------------- bf16x3 pipelined GEMM ----------------
// C = act(A @ Bt^T + bias + add0[idx0[row]] + add1[idx1[row]])
// MT=4: 128-row tile, 1 CTA/SM, fragment-level software pipelining in the mainloop
// MT=2/1: 64/32-row tile, 2 CTA/SM
template<int MT>
__global__ __launch_bounds__(256, (MT == 4 ? 1 : 2))
void mma_gemm_kernel(int M, int K, int ldb, int do_relu, int skip_mid,
                     const bf16* __restrict__ A0h, const bf16* __restrict__ A0l, int lda,
                     const bf16* __restrict__ Bh, const bf16* __restrict__ Bl,
                     const float* __restrict__ bias,
                     const float* __restrict__ add0, const int* __restrict__ idx0, int idx0s, int add0ld, int add0off,
                     const float* __restrict__ add1, const int* __restrict__ idx1, int idx1s, int add1ld, int add1off,
                     float* __restrict__ Cf, bf16* __restrict__ Ch, bf16* __restrict__ Cl, int ldc,
                     float* __restrict__ auxf, bf16* __restrict__ auxh, bf16* __restrict__ auxl,
                     int aux_lo, int aux_hi)
{
    constexpr int BM = 32 * MT;
    constexpr int ATILE = BM * ASTR;
    constexpr int BTILE = 128 * ASTR;
    constexpr int STAGE = 2 * ATILE + 2 * BTILE;

    extern __shared__ char smem[];
    const uint32_t sb = smem_u32(smem);
    const int tid = threadIdx.x;
    const int lane = tid & 31;
    const int wid = tid >> 5;
    const int bm = blockIdx.y * BM;
    const int bn = blockIdx.x * BN;

    const int c = tid & 7;
    const int rl = tid >> 3;
    const bf16* pAh[MT]; const bf16* pAl[MT];
    uint32_t asz[MT];
    #pragma unroll
    for (int i = 0; i < MT; i++) {
        int arow = bm + rl + 32 * i;
        bool v = arow < M;
        asz[i] = v ? 16u : 0u;
        int ar = v ? arow : 0;
        pAh[i] = A0h + (size_t)ar * lda;
        pAl[i] = A0l + (size_t)ar * lda;
    }
    const bf16* pBh[4]; const bf16* pBl[4];
    #pragma unroll
    for (int i = 0; i < 4; i++) {
        int r = bn + rl + 32 * i;
        pBh[i] = Bh + (size_t)r * ldb;
        pBl[i] = Bl + (size_t)r * ldb;
    }

    float acc[MT][4][4];
    #pragma unroll
    for (int a = 0; a < MT; a++)
        #pragma unroll
        for (int b = 0; b < 4; b++)
            #pragma unroll
            for (int d = 0; d < 4; d++) acc[a][b][d] = 0.f;

    const int wr = wid & 1;
    const int wc = wid >> 1;
    const uint32_t a_l_off = (uint32_t)((lane & 15) * ASTR + (lane >> 4) * 16);
    const uint32_t b_l_off = (uint32_t)((((lane & 7) + ((lane >> 4) << 3)) * ASTR) + (((lane >> 3) & 1) << 4));

    const int NT = K / BKC;

    auto issue = [&](int it) {
        const uint32_t st = sb + (uint32_t)(it & 1) * STAGE;
        const int k0 = it * BKC + c * 8;
        #pragma unroll
        for (int i = 0; i < MT; i++) {
            uint32_t d = st + (uint32_t)((rl + 32 * i) * ASTR + c * 16);
            cpa16(d,         pAh[i] + k0, asz[i]);
            cpa16(d + ATILE, pAl[i] + k0, asz[i]);
        }
        #pragma unroll
        for (int i = 0; i < 4; i++) {
            uint32_t d = st + 2 * ATILE + (uint32_t)((rl + 32 * i) * ASTR + c * 16);
            cpa16(d,         pBh[i] + k0, 16u);
            cpa16(d + BTILE, pBl[i] + k0, 16u);
        }
        cpa_commit();
    };

    issue(0);

    for (int it = 0; it < NT; it++) {
        if (it + 1 < NT) { issue(it + 1); cpa_wait<1>(); }
        else             { cpa_wait<0>(); }
        __syncthreads();

        const uint32_t st = sb + (uint32_t)(it & 1) * STAGE;
        const uint32_t aH = st + (uint32_t)(wr * 16 * MT * ASTR) + a_l_off;
        const uint32_t aL = aH + ATILE;
        const uint32_t bH = st + 2 * ATILE + (uint32_t)(wc * 32 * ASTR) + b_l_off;
        const uint32_t bL = bH + BTILE;

        if constexpr (MT == 4) {
            // ---- fragment-pipelined mainloop: LDSMs for group g+1 issue before MMAs of group g ----
            uint32_t afH[2][4][4], bfH[2][2][4];
            #pragma unroll
            for (int mt = 0; mt < 4; mt++) ldsm4(afH[0][mt], aH + (uint32_t)(mt * 16 * ASTR));
            #pragma unroll
            for (int np = 0; np < 2; np++) ldsm4(bfH[0][np], bH + (uint32_t)(np * 16 * ASTR));
            #pragma unroll
            for (int ks = 0; ks < 4; ks++) {
                const int cur = ks & 1, nxt = cur ^ 1;
                const uint32_t kb = ks * 32;
                uint32_t bfL[2][4], afL[4][4];
                // feed G2 before G1's MMAs
                #pragma unroll
                for (int np = 0; np < 2; np++) ldsm4(bfL[np], bL + (uint32_t)(np * 16 * ASTR) + kb);
                // G1: aH x bH
                #pragma unroll
                for (int mt = 0; mt < 4; mt++)
                    #pragma unroll
                    for (int np = 0; np < 2; np++) {
                        mma16816(acc[mt][2 * np],     afH[cur][mt], &bfH[cur][np][0]);
                        mma16816(acc[mt][2 * np + 1], afH[cur][mt], &bfH[cur][np][2]);
                    }
                // feed G3 before G2's MMAs
                #pragma unroll
                for (int mt = 0; mt < 4; mt++) ldsm4(afL[mt], aL + (uint32_t)(mt * 16 * ASTR) + kb);
                // G2: aH x bL
                #pragma unroll
                for (int mt = 0; mt < 4; mt++)
                    #pragma unroll
                    for (int np = 0; np < 2; np++) {
                        mma16816(acc[mt][2 * np],     afH[cur][mt], &bfL[np][0]);
                        mma16816(acc[mt][2 * np + 1], afH[cur][mt], &bfL[np][2]);
                    }
                // feed next k-step's G1 before G3's MMAs
                if (ks < 3) {
                    #pragma unroll
                    for (int mt = 0; mt < 4; mt++) ldsm4(afH[nxt][mt], aH + (uint32_t)(mt * 16 * ASTR) + kb + 32);
                    #pragma unroll
                    for (int np = 0; np < 2; np++) ldsm4(bfH[nxt][np], bH + (uint32_t)(np * 16 * ASTR) + kb + 32);
                }
                // G3: aL x bH
                #pragma unroll
                for (int mt = 0; mt < 4; mt++)
                    #pragma unroll
                    for (int np = 0; np < 2; np++) {
                        mma16816(acc[mt][2 * np],     afL[mt], &bfH[cur][np][0]);
                        mma16816(acc[mt][2 * np + 1], afL[mt], &bfH[cur][np][2]);
                    }
            }
        } else {
            #pragma unroll
            for (int ks = 0; ks < 4; ks++) {
                const uint32_t kb = ks * 32;
                uint32_t af[MT][4], bh2[2][4];
                #pragma unroll
                for (int mt = 0; mt < MT; mt++) ldsm4(af[mt], aH + (uint32_t)(mt * 16 * ASTR) + kb);
                #pragma unroll
                for (int np = 0; np < 2; np++) ldsm4(bh2[np], bH + (uint32_t)(np * 16 * ASTR) + kb);
                #pragma unroll
                for (int mt = 0; mt < MT; mt++)
                    #pragma unroll
                    for (int np = 0; np < 2; np++) {
                        mma16816(acc[mt][2 * np],     af[mt], &bh2[np][0]);
                        mma16816(acc[mt][2 * np + 1], af[mt], &bh2[np][2]);
                    }
                uint32_t bl2[2][4];
                #pragma unroll
                for (int np = 0; np < 2; np++) ldsm4(bl2[np], bL + (uint32_t)(np * 16 * ASTR) + kb);
                #pragma unroll
                for (int mt = 0; mt < MT; mt++)
                    #pragma unroll
                    for (int np = 0; np < 2; np++) {
                        mma16816(acc[mt][2 * np],     af[mt], &bl2[np][0]);
                        mma16816(acc[mt][2 * np + 1], af[mt], &bl2[np][2]);
                    }
                #pragma unroll
                for (int mt = 0; mt < MT; mt++) ldsm4(af[mt], aL + (uint32_t)(mt * 16 * ASTR) + kb);
                #pragma unroll
                for (int mt = 0; mt < MT; mt++)
                    #pragma unroll
                    for (int np = 0; np < 2; np++) {
                        mma16816(acc[mt][2 * np],     af[mt], &bh2[np][0]);
                        mma16816(acc[mt][2 * np + 1], af[mt], &bh2[np][2]);
                    }
            }
        }
        __syncthreads();
    }

    // ---- epilogue ----
    const int g = lane >> 2, qr = lane & 3;
    const int awidth = aux_hi - aux_lo;
    const float* a0p[MT][2];
    const float* a1p[MT][2];
    #pragma unroll
    for (int mt = 0; mt < MT; mt++)
        #pragma unroll
        for (int hh = 0; hh < 2; hh++) {
            int row = bm + wr * 16 * MT + mt * 16 + g + 8 * hh;
            int rr = (row < M) ? row : 0;
            a0p[mt][hh] = add0 ? add0 + (size_t)idx0[(size_t)rr * idx0s] * add0ld + add0off : nullptr;
            a1p[mt][hh] = add1 ? add1 + (size_t)idx1[(size_t)rr * idx1s] * add1ld + add1off : nullptr;
        }
    #pragma unroll
    for (int nt = 0; nt < 4; nt++) {
        const int col = bn + wc * 32 + nt * 8 + qr * 2;
        float2 bv = make_float2(0.f, 0.f);
        if (bias) bv = *reinterpret_cast<const float2*>(bias + col);
        const bool in_aux = (col >= aux_lo) && (col < aux_hi);
        #pragma unroll
        for (int mt = 0; mt < MT; mt++) {
            #pragma unroll
            for (int hh = 0; hh < 2; hh++) {
                const int row = bm + wr * 16 * MT + mt * 16 + g + 8 * hh;
                if (row >= M) continue;
                float v0 = acc[mt][nt][2 * hh]     + bv.x;
                float v1 = acc[mt][nt][2 * hh + 1] + bv.y;
                if (add0) {
                    float2 a = *reinterpret_cast<const float2*>(a0p[mt][hh] + col);
                    v0 += a.x; v1 += a.y;
                }
                if (add1) {
                    float2 a = *reinterpret_cast<const float2*>(a1p[mt][hh] + col);
                    v0 += a.x; v1 += a.y;
                }
                if (do_relu) { v0 = fmaxf(v0, 0.f); v1 = fmaxf(v1, 0.f); }
                if (Cf && !(skip_mid && in_aux))
                    *reinterpret_cast<float2*>(Cf + (size_t)row * ldc + col) = make_float2(v0, v1);
                if (Ch) {
                    bf16 h0, l0, h1, l1;
                    split1(v0, h0, l0); split1(v1, h1, l1);
                    __nv_bfloat162 ph; ph.x = h0; ph.y = h1;
                    __nv_bfloat162 pl; pl.x = l0; pl.y = l1;
                    *reinterpret_cast<__nv_bfloat162*>(Ch + (size_t)row * ldc + col) = ph;
                    *reinterpret_cast<__nv_bfloat162*>(Cl + (size_t)row * ldc + col) = pl;
                }
                if (in_aux) {
                    const int ac = col - aux_lo;
                    if (auxf)
                        *reinterpret_cast<float2*>(auxf + (size_t)row * awidth + ac) = make_float2(v0, v1);
                    if (auxh) {
                        bf16 h0, l0, h1, l1;
                        split1(v0, h0, l0); split1(v1, h1, l1);
                        __nv_bfloat162 ph; ph.x = h0; ph.y = h1;
                        __nv_bfloat162 pl; pl.x = l0; pl.y = l1;
                        *reinterpret_cast<__nv_bfloat162*>(auxh + (size_t)row * awidth + ac) = ph;
                        *reinterpret_cast<__nv_bfloat162*>(auxl + (size_t)row * awidth + ac) = pl;
                    }
                }
            }
        }
    }
}

// ---------------- mega prep kernels ----------------
struct TsJob { const float* src; bf16* dh; bf16* dl; int K, N, KP, tile0; };
struct TsArgs { TsJob j[32]; int nj; };
__global__ void mega_tsplit_kernel(TsArgs a) {
    const int b = blockIdx.x;
    int lo = 0;
    #pragma unroll 1
    for (int i = 1; i < a.nj; i++) if (a.j[i].tile0 <= b) lo = i;
    const TsJob jb = a.j[lo];
    const int t = b - jb.tile0;
    const int ntx = (jb.KP + 31) >> 5;
    const int tx = t % ntx, ty = t / ntx;
    __shared__ float tile[32][33];
    const int bk = tx * 32, bn = ty * 32;
    const int x = threadIdx.x & 31, y = threadIdx.x >> 5;
    for (int i = y; i < 32; i += 8) {
        int k = bk + i, n = bn + x;
        tile[i][x] = (k < jb.K && n < jb.N) ? jb.src[(size_t)k * jb.N + n] : 0.f;
    }
    __syncthreads();
    for (int i = y; i < 32; i += 8) {
        int n = bn + i, k = bk + x;
        if (n < jb.N && k < jb.KP) {
            float v = tile[x][i];
            bf16 hh, ll; split1(v, hh, ll);
            jb.dh[(size_t)n * jb.KP + k] = hh;
            jb.dl[(size_t)n * jb.KP + k] = ll;
        }
    }
}

struct SpJob { const float* src; bf16* dh; bf16* dl; int W, WP, n, blk0; };
struct SpArgs { SpJob j[4]; int nj; };
__global__ void mega_split_kernel(SpArgs a) {
    const int b = blockIdx.x;
    int lo = 0;
    #pragma unroll 1
    for (int i = 1; i < a.nj; i++) if (a.j[i].blk0 <= b) lo = i;
    const SpJob jb = a.j[lo];
    const int i = (b - jb.blk0) * 256 + threadIdx.x;
    if (i >= jb.n) return;
    const int v = i / jb.WP, c = i - v * jb.WP;
    float val = (c < jb.W) ? jb.src[(size_t)v * jb.W + c] : 0.f;
    bf16 hh, ll; split1(val, hh, ll);
    jb.dh[i] = hh; jb.dl[i] = ll;
}

// ---------------- deterministic scatter-mean pooling ----------------
__global__ void zero_int_kernel(int* p, int n) {
    int i = blockIdx.x * blockDim.x + threadIdx.x;
    if (i < n) p[i] = 0;
}
__global__ void build_count_kernel(const int* __restrict__ rels, int* __restrict__ objarr,
                                   int* __restrict__ cnt) {
    int e = blockIdx.x * blockDim.x + threadIdx.x;
    if (e >= E_N) return;
    int t = e >> 1;
    int v = rels[3 * t + ((e & 1) ? 2 : 0)];
    objarr[e] = v;
    atomicAdd(&cnt[v], 1);
}
__global__ void scan_kernel(const int* __restrict__ cnt, int* __restrict__ off,
                            float* __restrict__ inv) {
    __shared__ int buf[2][2048];
    int tid = threadIdx.x;
    for (int i = tid; i < 2048; i += 1024) {
        int c = (i < O_N) ? cnt[i] : 0;
        buf[0][i] = c;
        if (i < O_N) inv[i] = 1.0f / fmaxf((float)c, 1.0f);
    }
    __syncthreads();
    int src = 0;
    for (int d = 1; d < 2048; d <<= 1) {
        for (int i = tid; i < 2048; i += 1024) {
            int v = buf[src][i];
            if (i >= d) v += buf[src][i - d];
            buf[1 - src][i] = v;
        }
        src = 1 - src;
        __syncthreads();
    }
    for (int i = tid; i < O_N; i += 1024) off[i] = (i == 0) ? 0 : buf[src][i - 1];
    if (tid == 0) off[O_N] = buf[src][O_N - 1];
}
__global__ void rank_fill_kernel(const int* __restrict__ objarr, const int* __restrict__ off,
                                 int* __restrict__ entries) {
    int i = blockIdx.x * blockDim.x + threadIdx.x;
    if (i >= O_N) return;
    int w = off[i];
    for (int e = 0; e < E_N; e++)
        if (objarr[e] == i) entries[w++] = e;
}
// tbuf layout [T_N, 1536] = [new_s | new_p(skipped) | new_o]
__global__ void pool_gather_kernel(const float* __restrict__ t,
                                   const int* __restrict__ entries, const int* __restrict__ off,
                                   const float* __restrict__ inv,
                                   bf16* __restrict__ ph, bf16* __restrict__ pl) {
    int i = blockIdx.x;
    int c0 = threadIdx.x;
    int beg = off[i], end = off[i + 1];
    float s0 = 0.f, s1 = 0.f;
    for (int p = beg; p < end; p++) {
        int e = entries[p];
        int tr = e >> 1;
        const float* src = t + (size_t)tr * 1536 + ((e & 1) ? 1024 : 0);
        s0 += src[c0];
        s1 += src[c0 + 256];
    }
    float iv = inv[i];
    float v0 = s0 * iv, v1 = s1 * iv;
    bf16 h, l;
    split1(v0, h, l);
    ph[(size_t)i * 512 + c0] = h; pl[(size_t)i * 512 + c0] = l;
    split1(v1, h, l);
    ph[(size_t)i * 512 + c0 + 256] = h; pl[(size_t)i * 512 + c0 + 256] = l;
}

// ---------------- host glue ----------------
struct GPtr { bf16 *h, *l; };

#define SMEM_MT4 (2 * (2*128*ASTR + 2*128*ASTR))
#define SMEM_MT2 (2 * (2*64*ASTR + 2*128*ASTR))
#define SMEM_MT1 (2 * (2*32*ASTR + 2*128*ASTR))

struct AddArg { const float* p; const int* idx; int s; int ld; int off; };

static inline void run_mma(int MT, int M, int Ntot, int K, int ldb, int relu,
                           GPtr A0, int lda, GPtr Bt,
                           const float* bias,
                           float* Cf, GPtr C, int ldc,
                           AddArg a0 = {nullptr, nullptr, 0, 0, 0},
                           AddArg a1 = {nullptr, nullptr, 0, 0, 0},
                           float* auxf = nullptr, GPtr aux = {nullptr, nullptr},
                           int aux_lo = 0, int aux_hi = 0, int skip_mid = 0)
{
    if (MT == 4) {
        dim3 grid(Ntot / BN, (M + 127) / 128);
        mma_gemm_kernel<4><<<grid, 256, SMEM_MT4>>>(M, K, ldb, relu, skip_mid,
            A0.h, A0.l, lda, Bt.h, Bt.l, bias,
            a0.p, a0.idx, a0.s, a0.ld, a0.off,
            a1.p, a1.idx, a1.s, a1.ld, a1.off,
            Cf, C.h, C.l, ldc, auxf, aux.h, aux.l, aux_lo, aux_hi);
    } else if (MT == 2) {
        dim3 grid(Ntot / BN, (M + 63) / 64);
        mma_gemm_kernel<2><<<grid, 256, SMEM_MT2>>>(M, K, ldb, relu, skip_mid,
            A0.h, A0.l, lda, Bt.h, Bt.l, bias,
            a0.p, a0.idx, a0.s, a0.ld, a0.off,
            a1.p, a1.idx, a1.s, a1.ld, a1.off,
            Cf, C.h, C.l, ldc, auxf, aux.h, aux.l, aux_lo, aux_hi);
    } else {
        dim3 grid(Ntot / BN, (M + 31) / 32);
        mma_gemm_kernel<1><<<grid, 256, SMEM_MT1>>>(M, K, ldb, relu, skip_mid,
            A0.h, A0.l, lda, Bt.h, Bt.l, bias,
            a0.p, a0.idx, a0.s, a0.ld, a0.off,
            a1.p, a1.idx, a1.s, a1.ld, a1.off,
            Cf, C.h, C.l, ldc, auxf, aux.h, aux.l, aux_lo, aux_hi);
    }
}

extern "C" void kernel_launch(void* const* d_in, const int* in_sizes, int n_in,
                              void* d_out, int out_size)
{
    const float* obj_embs  = (const float*)d_in[0];
    const float* pred_embs = (const float*)d_in[2];
    const int*   rels      = (const int*)d_in[4];
    const int*   objs      = (const int*)d_in[5];
    const float* obj_table = (const float*)d_in[6];
    const float* rel_table = (const float*)d_in[7];
    const float* Wf_obj    = (const float*)d_in[8];
    const float* bf_obj    = (const float*)d_in[9];
    const float* Wf_rel    = (const float*)d_in[10];
    const float* bf_rel    = (const float*)d_in[11];
    const float* W1a       = (const float*)d_in[12];
    const float* b1a       = (const float*)d_in[13];
    const float* W1b       = (const float*)d_in[14];
    const float* b1b       = (const float*)d_in[15];
    const float* W2a       = (const float*)d_in[16];
    const float* b2a       = (const float*)d_in[17];
    const float* W2b       = (const float*)d_in[18];
    const float* b2b       = (const float*)d_in[19];
    const float* Ws1a      = (const float*)d_in[20];
    const float* bs1a      = (const float*)d_in[21];
    const float* Ws1b      = (const float*)d_in[22];
    const float* bs1b      = (const float*)d_in[23];
    const float* Ws2a      = (const float*)d_in[24];
    const float* bs2a      = (const float*)d_in[25];
    const float* Ws2b      = (const float*)d_in[26];
    const float* bs2b      = (const float*)d_in[27];
    float* out = (float*)d_out;

    cudaFuncSetAttribute(mma_gemm_kernel<4>, cudaFuncAttributeMaxDynamicSharedMemorySize, SMEM_MT4);
    cudaFuncSetAttribute(mma_gemm_kernel<2>, cudaFuncAttributeMaxDynamicSharedMemorySize, SMEM_MT2);
    cudaFuncSetAttribute(mma_gemm_kernel<1>, cudaFuncAttributeMaxDynamicSharedMemorySize, SMEM_MT1);

    auto sym = [](const void* s) { void* p; cudaGetSymbolAddress(&p, s); return p; };
    GPtr eobj  = {(bf16*)sym(g_eobj_h),  (bf16*)sym(g_eobj_l)};
    GPtr epred = {(bf16*)sym(g_epred_h), (bf16*)sym(g_epred_l)};
    GPtr tobj  = {(bf16*)sym(g_tobj_h),  (bf16*)sym(g_tobj_l)};
    GPtr trel  = {(bf16*)sym(g_trel_h),  (bf16*)sym(g_trel_l)};
    GPtr objA  = {(bf16*)sym(g_objA_h),  (bf16*)sym(g_objA_l)};
    GPtr pA    = {(bf16*)sym(g_pA_h),    (bf16*)sym(g_pA_l)};
    GPtr hb    = {(bf16*)sym(g_h_h),     (bf16*)sym(g_h_l)};
    GPtr p512  = {(bf16*)sym(g_p512_h),  (bf16*)sym(g_p512_l)};
    GPtr pool  = {(bf16*)sym(g_pool_h),  (bf16*)sym(g_pool_l)};
    GPtr o512  = {(bf16*)sym(g_o512_h),  (bf16*)sym(g_o512_l)};
    float* tblobj = (float*)sym(g_tblobj);
    float* tblrel = (float*)sym(g_tblrel);
    float* objSO  = (float*)sym(g_objSO);
    bf16* wth = (bf16*)sym(g_wt_h);
    bf16* wtl = (bf16*)sym(g_wt_l);
    float* tbuf = (float*)sym(g_t);
    int* cnt = (int*)sym(g_cnt);
    int* off = (int*)sym(g_off);
    int* objarr = (int*)sym(g_objarr);
    int* entries = (int*)sym(g_entries);
    float* finv = (float*)sym(g_inv);

    // weight pool (bf16 elems)
    size_t po = 0;
    auto take = [&](size_t n) { GPtr r = {wth + po, wtl + po}; po += n; return r; };
    GPtr tWfobj  = take((size_t)DIN * KP_EMB);
    GPtr tWfrel  = take((size_t)DIN * KP_EMB);
    GPtr tW1a_p  = take((size_t)H_DIM * DIN);
    GPtr tW1a_so = take((size_t)1024 * DIN);
    GPtr tW1b    = take((size_t)1536 * H_DIM);
    GPtr tW2a    = take((size_t)H_DIM * H_DIM);
    GPtr tW2b    = take((size_t)DG * H_DIM);
    GPtr tWs1a_p  = take((size_t)L_EXTRA * H_DIM * DG);
    GPtr tWs1a_so = take((size_t)L_EXTRA * 1024 * DG);
    GPtr tWs1b    = take((size_t)L_EXTRA * 1536 * H_DIM);
    GPtr tWs2a    = take((size_t)L_EXTRA * H_DIM * H_DIM);
    GPtr tWs2b    = take((size_t)L_EXTRA * DG * H_DIM);

    // --- mega prep: all weight transpose+splits in ONE launch ---
    TsArgs ta; ta.nj = 0;
    int tile0 = 0;
    auto addts = [&](const float* src, GPtr dst, int K, int N, int KP) {
        TsJob& j = ta.j[ta.nj++];
        j.src = src; j.dh = dst.h; j.dl = dst.l; j.K = K; j.N = N; j.KP = KP; j.tile0 = tile0;
        tile0 += ((KP + 31) / 32) * ((N + 31) / 32);
    };
    addts(Wf_obj, tWfobj, DIN + DW, DIN, KP_EMB);
    addts(Wf_rel, tWfrel, DIN + DW, DIN, KP_EMB);
    addts(W1a + (size_t)DIN * H_DIM, tW1a_p, DIN, H_DIM, DIN);
    addts(W1a, tW1a_so, DIN, H_DIM, DIN);
    addts(W1a + (size_t)2 * DIN * H_DIM, {tW1a_so.h + (size_t)H_DIM * DIN, tW1a_so.l + (size_t)H_DIM * DIN}, DIN, H_DIM, DIN);
    addts(W1b, tW1b, H_DIM, 1536, H_DIM);
    addts(W2a, tW2a, H_DIM, H_DIM, H_DIM);
    addts(W2b, tW2b, H_DIM, DG, H_DIM);
    for (int i = 0; i < L_EXTRA; i++) {
        const float* Wi = Ws1a + (size_t)i * 3 * DG * H_DIM;
        GPtr p_i  = {tWs1a_p.h + (size_t)i * H_DIM * DG,  tWs1a_p.l + (size_t)i * H_DIM * DG};
        GPtr so_i = {tWs1a_so.h + (size_t)i * 1024 * DG,  tWs1a_so.l + (size_t)i * 1024 * DG};
        addts(Wi + (size_t)DG * H_DIM, p_i, DG, H_DIM, DG);
        addts(Wi, so_i, DG, H_DIM, DG);
        addts(Wi + (size_t)2 * DG * H_DIM, {so_i.h + (size_t)H_DIM * DG, so_i.l + (size_t)H_DIM * DG}, DG, H_DIM, DG);
        addts(Ws1b + (size_t)i * H_DIM * 1536, {tWs1b.h + (size_t)i * 1536 * H_DIM, tWs1b.l + (size_t)i * 1536 * H_DIM}, H_DIM, 1536, H_DIM);
        addts(Ws2a + (size_t)i * H_DIM * H_DIM, {tWs2a.h + (size_t)i * H_DIM * H_DIM, tWs2a.l + (size_t)i * H_DIM * H_DIM}, H_DIM, H_DIM, H_DIM);
        addts(Ws2b + (size_t)i * H_DIM * DG, {tWs2b.h + (size_t)i * DG * H_DIM, tWs2b.l + (size_t)i * DG * H_DIM}, H_DIM, DG, H_DIM);
    }
    mega_tsplit_kernel<<<tile0, 256>>>(ta);

    // --- mega activation splits in ONE launch ---
    SpArgs sa; sa.nj = 0;
    int blk0 = 0;
    auto addsp = [&](const float* src, GPtr dst, int V, int W, int WP) {
        SpJob& j = sa.j[sa.nj++];
        j.src = src; j.dh = dst.h; j.dl = dst.l; j.W = W; j.WP = WP; j.n = V * WP; j.blk0 = blk0;
        blk0 += (V * WP + 255) / 256;
    };
    addsp(obj_embs, eobj, O_N, DIN, DIN);
    addsp(pred_embs, epred, T_N, DIN, DIN);
    addsp(obj_table, tobj, 1000, DW, DWP);
    addsp(rel_table, trel, 500, DW, DWP);
    mega_split_kernel<<<blk0, 256>>>(sa);

    // --- CSR for deterministic pooling ---
    zero_int_kernel<<<(O_N + 255) / 256, 256>>>(cnt, O_N);
    build_count_kernel<<<(E_N + 255) / 256, 256>>>(rels, objarr, cnt);
    scan_kernel<<<1, 1024>>>(cnt, off, finv);
    rank_fill_kernel<<<(O_N + 255) / 256, 256>>>(objarr, off, entries);

    GPtr nullg = {nullptr, nullptr};
    AddArg noadd = {nullptr, nullptr, 0, 0, 0};

    // --- table contributions ---
    run_mma(2, 1000, DIN, DWP, KP_EMB, 0, tobj, DWP,
            {tWfobj.h + DIN, tWfobj.l + DIN}, nullptr, tblobj, nullg, DIN);
    run_mma(1, 500, DIN, DWP, KP_EMB, 0, trel, DWP,
            {tWfrel.h + DIN, tWfrel.l + DIN}, nullptr, tblrel, nullg, DIN);

    // --- embedding GEMMs (MT=4, pipelined mainloop) ---
    run_mma(4, O_N, DIN, DIN, KP_EMB, 1, eobj, DIN, tWfobj, bf_obj,
            nullptr, objA, DIN, {tblobj, objs, 1, DIN, 0});
    run_mma(4, T_N, DIN, DIN, KP_EMB, 1, epred, DIN, tWfrel, bf_rel,
            nullptr, pA, DIN, {tblrel, rels + 1, 3, DIN, 0});

    // --- layer 0 ---
    run_mma(2, O_N, 1024, DIN, DIN, 0, objA, DIN, tW1a_so, nullptr,
            objSO, nullg, 1024);
    run_mma(2, T_N, H_DIM, DIN, DIN, 1, pA, DIN, tW1a_p, b1a,
            nullptr, hb, H_DIM,
            {objSO, rels, 3, 1024, 0}, {objSO, rels + 2, 3, 1024, 512});
    run_mma(4, T_N, 1536, H_DIM, H_DIM, 1, hb, H_DIM, tW1b, b1b,
            tbuf, nullg, 1536, noadd, noadd, nullptr, p512, 512, 1024, 1);
    pool_gather_kernel<<<O_N, 256>>>(tbuf, entries, off, finv, pool.h, pool.l);
    run_mma(1, O_N, H_DIM, H_DIM, H_DIM, 1, pool, 512, tW2a, b2a,
            nullptr, hb, H_DIM);
    run_mma(1, O_N, DG, H_DIM, H_DIM, 1, hb, 512, tW2b, b2b,
            nullptr, o512, DG);

    // --- extra layers ---
    for (int i = 0; i < L_EXTRA; i++) {
        const bool last = (i == L_EXTRA - 1);
        GPtr p_i  = {tWs1a_p.h + (size_t)i * H_DIM * DG,  tWs1a_p.l + (size_t)i * H_DIM * DG};
        GPtr so_i = {tWs1a_so.h + (size_t)i * 1024 * DG,  tWs1a_so.l + (size_t)i * 1024 * DG};
        GPtr w1b = {tWs1b.h + (size_t)i * 1536 * H_DIM,   tWs1b.l + (size_t)i * 1536 * H_DIM};
        GPtr w2a = {tWs2a.h + (size_t)i * H_DIM * H_DIM,  tWs2a.l + (size_t)i * H_DIM * H_DIM};
        GPtr w2b = {tWs2b.h + (size_t)i * DG * H_DIM,     tWs2b.l + (size_t)i * DG * H_DIM};

        run_mma(2, O_N, 1024, DG, DG, 0, o512, DG, so_i, nullptr,
                objSO, nullg, 1024);
        run_mma(2, T_N, H_DIM, DG, DG, 1, p512, DG, p_i, bs1a + (size_t)i * H_DIM,
                nullptr, hb, H_DIM,
                {objSO, rels, 3, 1024, 0}, {objSO, rels + 2, 3, 1024, 512});
        run_mma(4, T_N, 1536, H_DIM, H_DIM, 1, hb, H_DIM, w1b, bs1b + (size_t)i * 1536,
                tbuf, nullg, 1536, noadd, noadd,
                last ? (out + (size_t)O_N * DG) : nullptr,
                last ? nullg : p512, 512, 1024, 1);
        pool_gather_kernel<<<O_N, 256>>>(tbuf, entries, off, finv, pool.h, pool.l);
        run_mma(1, O_N, H_DIM, H_DIM, H_DIM, 1, pool, 512, w2a, bs2a + (size_t)i * H_DIM,
                nullptr, hb, H_DIM);
        run_mma(1, O_N, DG, H_DIM, H_DIM, 1, hb, 512, w2b, bs2b + (size_t)i * DG,
                last ? out : nullptr, last ? nullg : o512, DG);
    }
}